// round 12
// baseline (speedup 1.0000x reference)
#include <cuda_runtime.h>
#include <cuda_bf16.h>

// K1: zero the accumulator (out is poisoned by the harness).
__global__ __launch_bounds__(256)
void tmp_zero_kernel(float* __restrict__ out, int n_nodes) {
    int i = blockIdx.x * blockDim.x + threadIdx.x;
    if (i < n_nodes) out[i] = 0.0f;
}

// K2: fused seed + edge scatter. All writes to out are atomicAdd, so the two
// roles need no ordering. Edge warps process 2 tiles (64 edges) each with ALL
// loads (4 index + 8 float4 edge sweeps + 2 gathers) issued before any
// consumption -> ~2x deeper in-flight window, keeping DRAM requests
// outstanding through the dependent shfl/atomic phase.
__global__ __launch_bounds__(256)
void tmp_fused_kernel(const float* __restrict__ nodes,
                      const float* __restrict__ edges,
                      const int*   __restrict__ senders,
                      const int*   __restrict__ receivers,
                      const float* __restrict__ w_node_p,
                      const float* __restrict__ w_edge_p,
                      const float* __restrict__ b_node_p,
                      float* __restrict__ out,
                      int n_nodes, int n_edges, int d_node, int d_edge,
                      int seed_blocks) {
    const float wn = __ldg(w_node_p);
    const float we = __ldg(w_edge_p);

    if (blockIdx.x < (unsigned)seed_blocks) {
        // ---- Seed role: out[i] += wn*nodes[i,0] + bn ----
        const float bn = __ldg(b_node_p);
        int i = blockIdx.x * blockDim.x + threadIdx.x;
        if (i < n_nodes) {
            float v = __ldg(nodes + (size_t)i * d_node);
            atomicAdd(out + i, fmaf(wn, v, bn));
        }
        return;
    }

    // ---- Edge role: 64 edges per warp (2 tiles of 32) ----
    const int ebid        = blockIdx.x - seed_blocks;
    const int etid        = ebid * blockDim.x + threadIdx.x;
    const int warp_global = etid >> 5;
    const int lane        = etid & 31;
    const int base        = warp_global * 64;

    if (base >= n_edges) return;

    if (base + 64 <= n_edges && d_edge == 16) {
        const int e0 = base + lane;
        const int e1 = base + 32 + lane;

        // --- Issue ALL loads up front (coalesced) ---
        const int s0 = __ldcs(senders + e0);
        const int r0 = __ldcs(receivers + e0);
        const int s1 = __ldcs(senders + e1);
        const int r1 = __ldcs(receivers + e1);

        const float4* ef4 = (const float4*)edges;
        const size_t fb0 = (size_t)base * 4;         // tile 0: floats4 [fb0, fb0+128)
        const size_t fb1 = fb0 + 128;                // tile 1
        float4 q0 = __ldcs(ef4 + fb0 + 0 * 32 + lane);
        float4 q1 = __ldcs(ef4 + fb0 + 1 * 32 + lane);
        float4 q2 = __ldcs(ef4 + fb0 + 2 * 32 + lane);
        float4 q3 = __ldcs(ef4 + fb0 + 3 * 32 + lane);
        float4 q4 = __ldcs(ef4 + fb1 + 0 * 32 + lane);
        float4 q5 = __ldcs(ef4 + fb1 + 1 * 32 + lane);
        float4 q6 = __ldcs(ef4 + fb1 + 2 * 32 + lane);
        float4 q7 = __ldcs(ef4 + fb1 + 3 * 32 + lane);

        // Gathers (dependent on index loads, issued ASAP).
        const float nv0 = __ldg(nodes + (size_t)s0 * d_node);
        const float nv1 = __ldg(nodes + (size_t)s1 * d_node);

        // --- Consume tile 0 ---
        // Lane L wants edge base+L: sweep L/8, src lane (L%8)*4, comp .x.
        const int src = (lane & 7) * 4;
        const int sel = lane >> 3;
        {
            float t0 = __shfl_sync(0xffffffffu, q0.x, src);
            float t1 = __shfl_sync(0xffffffffu, q1.x, src);
            float t2 = __shfl_sync(0xffffffffu, q2.x, src);
            float t3 = __shfl_sync(0xffffffffu, q3.x, src);
            float ev = (sel == 0) ? t0 : (sel == 1) ? t1 : (sel == 2) ? t2 : t3;
            atomicAdd(out + r0, fmaf(we, ev, wn * nv0));
        }
        // --- Consume tile 1 ---
        {
            float t0 = __shfl_sync(0xffffffffu, q4.x, src);
            float t1 = __shfl_sync(0xffffffffu, q5.x, src);
            float t2 = __shfl_sync(0xffffffffu, q6.x, src);
            float t3 = __shfl_sync(0xffffffffu, q7.x, src);
            float ev = (sel == 0) ? t0 : (sel == 1) ? t1 : (sel == 2) ? t2 : t3;
            atomicAdd(out + r1, fmaf(we, ev, wn * nv1));
        }
    } else {
        // Tail / generic path: one edge per lane per tile.
        for (int t = 0; t < 2; ++t) {
            const int e = base + t * 32 + lane;
            if (e < n_edges) {
                const int s = __ldg(senders + e);
                const int r = __ldg(receivers + e);
                const float ev = __ldg(edges + (size_t)e * d_edge);
                const float nv = __ldg(nodes + (size_t)s * d_node);
                atomicAdd(out + r, fmaf(we, ev, wn * nv));
            }
        }
    }
}

extern "C" void kernel_launch(void* const* d_in, const int* in_sizes, int n_in,
                              void* d_out, int out_size) {
    const float* nodes     = (const float*)d_in[0];
    const float* edges     = (const float*)d_in[1];
    const int*   senders   = (const int*)  d_in[2];
    const int*   receivers = (const int*)  d_in[3];
    const float* w_node    = (const float*)d_in[4];
    const float* w_edge    = (const float*)d_in[5];
    const float* b_node    = (const float*)d_in[6];
    float*       out       = (float*)d_out;

    const int n_nodes = out_size;
    const int n_edges = in_sizes[2];
    const int d_node  = in_sizes[0] / n_nodes;   // 128
    const int d_edge  = in_sizes[1] / n_edges;   // 16

    const int threads = 256;

    // K1: zero the accumulator.
    {
        int blocks = (n_nodes + threads - 1) / threads;
        tmp_zero_kernel<<<blocks, threads>>>(out, n_nodes);
    }

    // K2: fused seed + edge scatter (64 edges per warp).
    {
        int seed_blocks = (n_nodes + threads - 1) / threads;                 // 391
        int edges_per_block = (threads / 32) * 64;                           // 512
        int edge_blocks = (n_edges + edges_per_block - 1) / edges_per_block; // 6250
        tmp_fused_kernel<<<seed_blocks + edge_blocks, threads>>>(
            nodes, edges, senders, receivers,
            w_node, w_edge, b_node, out,
            n_nodes, n_edges, d_node, d_edge, seed_blocks);
    }
}

// round 17
// speedup vs baseline: 1.0316x; 1.0316x over previous
#include <cuda_runtime.h>
#include <cuda_bf16.h>

#define MAX_NODES 1048576
__device__ float g_nodecol[MAX_NODES];   // packed nodes[:,0], rebuilt every launch

// K1: out[i] = w_node*nodes[i,0] + b_node, and pack nodes[:,0] into g_nodecol.
// 128-thread blocks -> 782 blocks: full chip coverage, ~21 warps/SM in one
// wave, each warp exposing 32 strided-sector loads (plenty of MLP).
__global__ __launch_bounds__(128)
void tmp_init_kernel(const float* __restrict__ nodes,
                     const float* __restrict__ w_node_p,
                     const float* __restrict__ b_node_p,
                     float* __restrict__ out,
                     int n_nodes, int d_node) {
    int i = blockIdx.x * blockDim.x + threadIdx.x;
    if (i < n_nodes) {
        float wn = __ldg(w_node_p);
        float bn = __ldg(b_node_p);
        float v  = __ldg(nodes + (size_t)i * d_node);
        g_nodecol[i] = v;
        out[i] = fmaf(wn, v, bn);
    }
}

// K2: warp-cooperative edge scatter (measured 42.8us twice).
// - 32 edges/warp; edge rows read as 4 coalesced float4 sweeps (evict-first
//   streaming so they don't pollute L1), element 0 redistributed via shfl.
// - Sender gather hits packed 400KB g_nodecol via the read-only path:
//   dense lines (32 useful floats per 128B) and mostly L1-resident, removing
//   ~half the scattered L2 requests.
// - Receiver scatter: fire-and-forget atomicAdd (REDG, spread addresses).
__global__ __launch_bounds__(256)
void tmp_edge_kernel(const float* __restrict__ edges,
                     const int*   __restrict__ senders,
                     const int*   __restrict__ receivers,
                     const float* __restrict__ w_node_p,
                     const float* __restrict__ w_edge_p,
                     float* __restrict__ out,
                     int n_edges, int d_edge) {
    const float wn = __ldg(w_node_p);
    const float we = __ldg(w_edge_p);

    const int tid         = blockIdx.x * blockDim.x + threadIdx.x;
    const int warp_global = tid >> 5;
    const int lane        = tid & 31;
    const int base        = warp_global * 32;

    if (base >= n_edges) return;

    if (base + 32 <= n_edges && d_edge == 16) {
        // Coalesced index loads: one edge per lane.
        const int e = base + lane;
        const int s = __ldcs(senders + e);
        const int r = __ldcs(receivers + e);

        // 4 coalesced float4 sweeps over the warp's 2KB of edge rows.
        const float4* ef4 = (const float4*)edges;
        const size_t f4base = (size_t)base * 4;
        float4 q0 = __ldcs(ef4 + f4base + 0 * 32 + lane);
        float4 q1 = __ldcs(ef4 + f4base + 1 * 32 + lane);
        float4 q2 = __ldcs(ef4 + f4base + 2 * 32 + lane);
        float4 q3 = __ldcs(ef4 + f4base + 3 * 32 + lane);

        // Gather from the packed column via the read-only (L1-cached) path.
        // Safe: g_nodecol written only by K1; L1 flushed at launch boundary.
        const float nv = __ldg(&g_nodecol[s]);

        // Lane L wants edge base+L: sweep L/8, src lane (L%8)*4, comp .x.
        const int src = (lane & 7) * 4;
        float t0 = __shfl_sync(0xffffffffu, q0.x, src);
        float t1 = __shfl_sync(0xffffffffu, q1.x, src);
        float t2 = __shfl_sync(0xffffffffu, q2.x, src);
        float t3 = __shfl_sync(0xffffffffu, q3.x, src);
        const int sel = lane >> 3;
        float ev = (sel == 0) ? t0 : (sel == 1) ? t1 : (sel == 2) ? t2 : t3;

        atomicAdd(out + r, fmaf(we, ev, wn * nv));
    } else {
        // Tail / generic path
        const int e = base + lane;
        if (e < n_edges) {
            const int s = __ldg(senders + e);
            const int r = __ldg(receivers + e);
            const float ev = __ldg(edges + (size_t)e * d_edge);
            const float nv = __ldg(&g_nodecol[s]);
            atomicAdd(out + r, fmaf(we, ev, wn * nv));
        }
    }
}

extern "C" void kernel_launch(void* const* d_in, const int* in_sizes, int n_in,
                              void* d_out, int out_size) {
    const float* nodes     = (const float*)d_in[0];
    const float* edges     = (const float*)d_in[1];
    const int*   senders   = (const int*)  d_in[2];
    const int*   receivers = (const int*)  d_in[3];
    const float* w_node    = (const float*)d_in[4];
    const float* w_edge    = (const float*)d_in[5];
    const float* b_node    = (const float*)d_in[6];
    float*       out       = (float*)d_out;

    const int n_nodes = out_size;
    const int n_edges = in_sizes[2];
    const int d_node  = in_sizes[0] / n_nodes;   // 128
    const int d_edge  = in_sizes[1] / n_edges;   // 16

    // K1: seed output and pack nodes[:,0] (1 node/thread, 128-thread blocks).
    {
        int threads = 128;
        int blocks  = (n_nodes + threads - 1) / threads;   // 782
        tmp_init_kernel<<<blocks, threads>>>(nodes, w_node, b_node, out, n_nodes, d_node);
    }

    // K2: scatter-add messages (32 edges per warp, warp-cooperative).
    {
        int threads = 256;                        // 8 warps/block
        int edges_per_block = (threads / 32) * 32;
        int blocks = (n_edges + edges_per_block - 1) / edges_per_block;
        tmp_edge_kernel<<<blocks, threads>>>(edges, senders, receivers,
                                             w_node, w_edge, out,
                                             n_edges, d_edge);
    }
}